// round 15
// baseline (speedup 1.0000x reference)
#include <cuda_runtime.h>
#include <cuda_bf16.h>
#include <cstdint>

#define BATCH 8192
#define NSTEPS 100
#define NCTAS 128
#define NTHREADS 512
#define DT_C 0.01f
#define SQDT_C 0.1f

// float-unit offsets. Fused-fragment layout: every 16B unit holds
// [hi0, hi1, lo0, lo1] bf16x2 words so a fragment (hi+lo pair) is ONE
// LDS.128. h planes pair-interleave klines (2k,2k+1) the same way.
// Groups: warps 4g..4g+3 own rows 16g..16g+15 (disjoint X/H/NZ/STG
// regions; weights shared read-only; private named barriers).
#define OFF_X    0      // x: 4 klines x 64 rows x 16 (hi/lo interleaved)
#define OFF_HD   4096   // h drift: 4 klpairs x 64 rows x 16
#define OFF_HG   8192
#define OFF_W1D  12288  // W1^T: 4 klines x 128 rows x 16 (hi/lo)
#define OFF_W1G  20480
#define OFF_W2D  28672  // W2^T: 8 klines x 64 rows x 16 (hi/lo)
#define OFF_W2G  36864
#define OFF_STG  45056  // g accum staging, 8 x 512 fp32 (2 per group)
#define OFF_NZ   49152  // noise 64x64 fp32 (xor-swizzled rows)
#define OFF_B2D  53248
#define OFF_B2G  53312
#define OFF_B1D  53376
#define OFF_B1G  53504
#define SMEM_FLOATS 53632
#define SMEM_BYTES (SMEM_FLOATS * 4)

__device__ __forceinline__ int slot8(int u) { return 2 * (u & 3) + (u >> 2); }
// old slot s -> fused position of hi word; lo word = +2
__device__ __forceinline__ int fpos(int s) {
    return ((s >> 1) << 2) + (s & 1);
}
__device__ __forceinline__ uint32_t pack_bf16x2(float lo, float hi) {
    uint32_t r;
    asm("cvt.rn.bf16x2.f32 %0, %1, %2;" : "=r"(r) : "f"(hi), "f"(lo));
    return r;
}
// accurate tanh: 1 - 2/(e^{2x}+1)
__device__ __forceinline__ float tanh_fast(float x) {
    float t = __expf(2.0f * x);
    return 1.0f - __fdividef(2.0f, t + 1.0f);
}
__device__ __forceinline__ void mma16(float* c, uint32_t a0, uint32_t a1,
                                      uint32_t a2, uint32_t a3, uint32_t b0,
                                      uint32_t b1) {
    asm volatile(
        "mma.sync.aligned.m16n8k16.row.col.f32.bf16.bf16.f32 "
        "{%0,%1,%2,%3},{%4,%5,%6,%7},{%8,%9},{%0,%1,%2,%3};\n"
        : "+f"(c[0]), "+f"(c[1]), "+f"(c[2]), "+f"(c[3])
        : "r"(a0), "r"(a1), "r"(a2), "r"(a3), "r"(b0), "r"(b1));
}
// split (v0,v1) into hi/lo bf16x2 words; hi+lo reconstructs v to ~2^-17
__device__ __forceinline__ void wsplit(float v0, float v1, uint32_t& hi,
                                       uint32_t& lo) {
    hi = pack_bf16x2(v0, v1);
    __nv_bfloat162 h2 = *(__nv_bfloat162*)&hi;
    lo = pack_bf16x2(v0 - __bfloat162float(h2.x), v1 - __bfloat162float(h2.y));
}
__device__ __forceinline__ void barsync(int id) {
    asm volatile("bar.sync %0, %1;" ::"r"(id), "r"(128) : "memory");
}
__device__ __forceinline__ void bararrive(int id) {
    asm volatile("bar.arrive %0, %1;" ::"r"(id), "r"(128) : "memory");
}

__global__ void __launch_bounds__(NTHREADS, 1) sde_kernel(
    const float* __restrict__ x0, const float* __restrict__ noise,
    const float* __restrict__ Wd1, const float* __restrict__ bd1,
    const float* __restrict__ Wd2, const float* __restrict__ bd2,
    const float* __restrict__ Wg1, const float* __restrict__ bg1,
    const float* __restrict__ Wg2, const float* __restrict__ bg2,
    float* __restrict__ out) {
    extern __shared__ float sm[];
    const int tid = threadIdx.x;
    const int warp = tid >> 5, lane = tid & 31, g = lane >> 2, tg = lane & 3;
    const int rowBase = blockIdx.x * 64;
    const int grp = warp >> 2;  // group: rows 16*grp .. 16*grp+15
    const int wg = warp & 3;    // warp within group
    const int ht = tid & 127;   // thread within group

    // ── init: W1 fused planes ───────────────────────────────────────
    for (int i = tid; i < 4096; i += NTHREADS) {  // pairs (k,k+1) x n
        int n = i & 127, kp = i >> 7, k = 2 * kp;
        int kl = kp >> 3, s = slot8(kp & 7);
        int idx = kl * 2048 + n * 16 + fpos(s);
        uint32_t hi, lo;
        wsplit(Wd1[k * 128 + n], Wd1[(k + 1) * 128 + n], hi, lo);
        *(uint32_t*)&sm[OFF_W1D + idx] = hi;
        *(uint32_t*)&sm[OFF_W1D + idx + 2] = lo;
        wsplit(Wg1[k * 128 + n], Wg1[(k + 1) * 128 + n], hi, lo);
        *(uint32_t*)&sm[OFF_W1G + idx] = hi;
        *(uint32_t*)&sm[OFF_W1G + idx + 2] = lo;
    }
    // W2 fused planes
    for (int i = tid; i < 4096; i += NTHREADS) {
        int n = i & 63, kp = i >> 6, k = 2 * kp;
        int kl = kp >> 3, s = slot8(kp & 7);
        int idx = kl * 1024 + n * 16 + fpos(s);
        uint32_t hi, lo;
        wsplit(Wd2[k * 64 + n], Wd2[(k + 1) * 64 + n], hi, lo);
        *(uint32_t*)&sm[OFF_W2D + idx] = hi;
        *(uint32_t*)&sm[OFF_W2D + idx + 2] = lo;
        wsplit(Wg2[k * 64 + n], Wg2[(k + 1) * 64 + n], hi, lo);
        *(uint32_t*)&sm[OFF_W2G + idx] = hi;
        *(uint32_t*)&sm[OFF_W2G + idx + 2] = lo;
    }
    for (int i = tid; i < 128; i += NTHREADS) {
        sm[OFF_B1D + i] = bd1[i];
        sm[OFF_B1G + i] = bg1[i];
    }
    for (int i = tid; i < 64; i += NTHREADS) {
        sm[OFF_B2D + i] = bd2[i];
        sm[OFF_B2G + i] = bg2[i];
    }
    // x0 -> fused hi/lo planes + out[0]
    for (int i = tid; i < 2048; i += NTHREADS) {  // col pairs
        int r = i >> 5, cp = i & 31, c = 2 * cp;
        float v0 = x0[(rowBase + r) * 64 + c];
        float v1 = x0[(rowBase + r) * 64 + c + 1];
        int kl = cp >> 3, s = slot8(cp & 7);
        int idx = kl * 1024 + r * 16 + fpos(s);
        uint32_t hi, lo;
        wsplit(v0, v1, hi, lo);
        *(uint32_t*)&sm[OFF_X + idx] = hi;
        *(uint32_t*)&sm[OFF_X + idx + 2] = lo;
        *(float2*)&out[(rowBase + r) * 64 + c] = make_float2(v0, v1);
    }

    // phase A (4 warps/group): 16r x 32c tile; warp wg -> klines 2wg,2wg+1
    // phase B (per group): warps 0,1 = drift(f), 2,3 = diffusion(g),
    //   tile 16x32 over (16 x 64); col half = wg&1
    const int wq = wg & 1;
    const int bR = 16 * grp, bC = 32 * wq;
    const bool isF = (wg < 2);
    const int bar1 = 3 * grp + 1, bar2 = 3 * grp + 2, bar3 = 3 * grp + 3;

    // fp32 x state lives in f-warp registers (2 warps x 16 elems per group)
    float2 xr[4][2];  // [n][rg]: cols bC+8n+2tg, rows bR+8rg+g
    if (isF) {
#pragma unroll
        for (int n = 0; n < 4; n++)
#pragma unroll
            for (int rg = 0; rg < 2; rg++) {
                int row = rowBase + bR + 8 * rg + g;
                xr[n][rg] =
                    *(const float2*)&x0[row * 64 + bC + 8 * n + 2 * tg];
            }
    }
    __syncthreads();

#pragma unroll 1
    for (int step = 0; step < NSTEPS; ++step) {
        // ── noise prefetch: group loads its own 16 rows (cp.async) ──
        {
            const float* nzg = noise + ((size_t)step * BATCH + rowBase) * 64;
#pragma unroll
            for (int j = 0; j < 2; j++) {
                int i = j * 128 + ht;  // 256 16B chunks per group
                int r = 16 * grp + (i >> 4);
                int c4 = (i & 15) * 4;
                float* dst = sm + OFF_NZ + r * 64 + (c4 ^ (8 * (r & 7)));
                uint32_t da;
                asm("{.reg .u64 t; cvta.to.shared.u64 t, %1; cvt.u32.u64 %0, t;}"
                    : "=r"(da) : "l"(dst));
                asm volatile("cp.async.ca.shared.global [%0], [%1], 16;\n" ::
                                 "r"(da), "l"(nzg + r * 64 + c4));
            }
            asm volatile("cp.async.commit_group;\n");
        }

        // ── phase A: h_d, h_g = tanh(x@W1 + b1); 16x32 tile per warp ─
        // error-compensated: Ah*Wh + Ah*Wl + Al*Wh  (fused LDS.128 frags)
        {
            float ca[2][4][4];  // [mat][nn][4]
#pragma unroll
            for (int a_ = 0; a_ < 2; a_++)
#pragma unroll
                for (int b_ = 0; b_ < 4; b_++)
#pragma unroll
                    for (int j = 0; j < 4; j++) ca[a_][b_][j] = 0.f;
#pragma unroll
            for (int kl = 0; kl < 4; kl++) {
                int r = 16 * grp + g;
                uint4 v0 = *(const uint4*)(sm + OFF_X + kl * 1024 + r * 16 + 4 * tg);
                uint4 v1 = *(const uint4*)(sm + OFF_X + kl * 1024 + (r + 8) * 16 + 4 * tg);
#pragma unroll
                for (int nn = 0; nn < 4; nn++) {
                    int wr = kl * 2048 + (32 * wg + 8 * nn + g) * 16 + 4 * tg;
                    uint4 wd = *(const uint4*)(sm + OFF_W1D + wr);
                    uint4 wgv = *(const uint4*)(sm + OFF_W1G + wr);
                    mma16(ca[0][nn], v0.x, v1.x, v0.y, v1.y, wd.x, wd.y);
                    mma16(ca[0][nn], v0.x, v1.x, v0.y, v1.y, wd.z, wd.w);
                    mma16(ca[0][nn], v0.z, v1.z, v0.w, v1.w, wd.x, wd.y);
                    mma16(ca[1][nn], v0.x, v1.x, v0.y, v1.y, wgv.x, wgv.y);
                    mma16(ca[1][nn], v0.x, v1.x, v0.y, v1.y, wgv.z, wgv.w);
                    mma16(ca[1][nn], v0.z, v1.z, v0.w, v1.w, wgv.x, wgv.y);
                }
            }
            // epilogue: bias + tanh + pack; one STS.128 per (mat, rg)
#pragma unroll
            for (int mat = 0; mat < 2; mat++) {
                float* hpb = sm + (mat ? OFF_HG : OFF_HD);
                const float* b1 = sm + (mat ? OFF_B1G : OFF_B1D);
                int cbA = 32 * wg + 2 * tg;
                float a00 = b1[cbA], a01 = b1[cbA + 1];
                float a10 = b1[cbA + 8], a11 = b1[cbA + 9];
                float c00 = b1[cbA + 16], c01 = b1[cbA + 17];
                float c10 = b1[cbA + 24], c11 = b1[cbA + 25];
#pragma unroll
                for (int rg = 0; rg < 2; rg++) {
                    int row = 16 * grp + 8 * rg + g;
                    float t0 = tanh_fast(ca[mat][0][2 * rg] + a00);
                    float t1 = tanh_fast(ca[mat][0][2 * rg + 1] + a01);
                    float t2 = tanh_fast(ca[mat][1][2 * rg] + a10);
                    float t3 = tanh_fast(ca[mat][1][2 * rg + 1] + a11);
                    float u0 = tanh_fast(ca[mat][2][2 * rg] + c00);
                    float u1 = tanh_fast(ca[mat][2][2 * rg + 1] + c01);
                    float u2 = tanh_fast(ca[mat][3][2 * rg] + c10);
                    float u3 = tanh_fast(ca[mat][3][2 * rg + 1] + c11);
                    uint4 st;
                    st.x = pack_bf16x2(t0, t1);
                    st.y = pack_bf16x2(t2, t3);
                    st.z = pack_bf16x2(u0, u1);
                    st.w = pack_bf16x2(u2, u3);
                    *(uint4*)(hpb + wg * 1024 + row * 16 + 4 * tg) = st;
                }
            }
        }
        barsync(bar1);  // S1 (group-scope): this group's h ready

        // ── phase B: y = h @ W2 (hi+lo), 16x32 tile, fused frags ────
        float cb[4][4];
        {
            const float* hp = sm + (isF ? OFF_HD : OFF_HG);
            const float* w2 = sm + (isF ? OFF_W2D : OFF_W2G);
#pragma unroll
            for (int n = 0; n < 4; n++)
#pragma unroll
                for (int j = 0; j < 4; j++) cb[n][j] = 0.f;
#pragma unroll
            for (int klp = 0; klp < 4; klp++) {
                uint4 a0 = *(const uint4*)(hp + klp * 1024 + (bR + g) * 16 + 4 * tg);
                uint4 a1 = *(const uint4*)(hp + klp * 1024 + (bR + 8 + g) * 16 + 4 * tg);
#pragma unroll
                for (int n = 0; n < 4; n++) {  // kline 2*klp
                    uint4 w = *(const uint4*)(w2 + (2 * klp) * 1024 +
                                              (bC + 8 * n + g) * 16 + 4 * tg);
                    mma16(cb[n], a0.x, a1.x, a0.y, a1.y, w.x, w.y);
                    mma16(cb[n], a0.x, a1.x, a0.y, a1.y, w.z, w.w);
                }
#pragma unroll
                for (int n = 0; n < 4; n++) {  // kline 2*klp+1
                    uint4 w = *(const uint4*)(w2 + (2 * klp + 1) * 1024 +
                                              (bC + 8 * n + g) * 16 + 4 * tg);
                    mma16(cb[n], a0.z, a1.z, a0.w, a1.w, w.x, w.y);
                    mma16(cb[n], a0.z, a1.z, a0.w, a1.w, w.z, w.w);
                }
            }
        }
        if (!isF) {
            // raw g accums -> staging (f-warp of same wq+grp reads it)
#pragma unroll
            for (int n = 0; n < 4; n++)
                *(float4*)(sm + OFF_STG + (grp * 2 + wq) * 512 + n * 128 +
                           lane * 4) = *(float4*)cb[n];
            asm volatile("cp.async.wait_group 0;\n");
            bararrive(bar2);
        } else {
            asm volatile("cp.async.wait_group 0;\n");
            barsync(bar2);  // wait this group's g + noise
            // ── combine: x += (f+bd2)*dt + (g+bg2)*dw*sqrt(dt) ──────
            float* op = out + ((size_t)(step + 1) * BATCH + rowBase) * 64;
            const float* gst =
                sm + OFF_STG + (grp * 2 + wq) * 512 + lane * 4;
            float4 gv[4];
#pragma unroll
            for (int n = 0; n < 4; n++) gv[n] = *(const float4*)(gst + n * 128);
#pragma unroll
            for (int np = 0; np < 2; np++) {
                int n0 = 2 * np, n1 = n0 + 1;
                int cc0 = bC + 8 * n0 + 2 * tg, cc1 = cc0 + 8;
                float bd0 = sm[OFF_B2D + cc0], bd1v = sm[OFF_B2D + cc0 + 1];
                float bd2_ = sm[OFF_B2D + cc1], bd3 = sm[OFF_B2D + cc1 + 1];
                float bg0 = sm[OFF_B2G + cc0], bg1v = sm[OFF_B2G + cc0 + 1];
                float bg2_ = sm[OFF_B2G + cc1], bg3 = sm[OFF_B2G + cc1 + 1];
#pragma unroll
                for (int rg = 0; rg < 2; rg++) {
                    int row = bR + 8 * rg + g;
                    float2 nz0 = *(const float2*)(sm + OFF_NZ + row * 64 + (cc0 ^ (8 * g)));
                    float2 nz1 = *(const float2*)(sm + OFF_NZ + row * 64 + (cc1 ^ (8 * g)));
                    float f0 = cb[n0][2 * rg] + bd0, f1 = cb[n0][2 * rg + 1] + bd1v;
                    float f2 = cb[n1][2 * rg] + bd2_, f3 = cb[n1][2 * rg + 1] + bd3;
                    float gg0 = (rg ? gv[n0].z : gv[n0].x) + bg0;
                    float gg1 = (rg ? gv[n0].w : gv[n0].y) + bg1v;
                    float gg2 = (rg ? gv[n1].z : gv[n1].x) + bg2_;
                    float gg3 = (rg ? gv[n1].w : gv[n1].y) + bg3;
                    float xn0 = xr[n0][rg].x + f0 * DT_C + gg0 * (nz0.x * SQDT_C);
                    float xn1 = xr[n0][rg].y + f1 * DT_C + gg1 * (nz0.y * SQDT_C);
                    float xn2 = xr[n1][rg].x + f2 * DT_C + gg2 * (nz1.x * SQDT_C);
                    float xn3 = xr[n1][rg].y + f3 * DT_C + gg3 * (nz1.y * SQDT_C);
                    xr[n0][rg] = make_float2(xn0, xn1);
                    xr[n1][rg] = make_float2(xn2, xn3);
                    *(float2*)(op + row * 64 + cc0) = make_float2(xn0, xn1);
                    *(float2*)(op + row * 64 + cc1) = make_float2(xn2, xn3);
                    // refresh fused x plane: one STS.128 (kline 2wq+np)
                    uint32_t h01, l01, h23, l23;
                    wsplit(xn0, xn1, h01, l01);
                    wsplit(xn2, xn3, h23, l23);
                    uint4 xs;
                    xs.x = h01;
                    xs.y = h23;
                    xs.z = l01;
                    xs.w = l23;
                    *(uint4*)(sm + OFF_X + (2 * wq + np) * 1024 + row * 16 +
                              4 * tg) = xs;
                }
            }
        }
        barsync(bar3);  // S2 (group-scope): this group's x ready
    }
}

extern "C" void kernel_launch(void* const* d_in, const int* in_sizes, int n_in,
                              void* d_out, int out_size) {
    (void)in_sizes; (void)n_in; (void)out_size;
    const float* x0 = (const float*)d_in[0];
    // d_in[1] = t_span (unused)
    const float* noise = (const float*)d_in[2];
    const float* Wd1 = (const float*)d_in[3];
    const float* bd1 = (const float*)d_in[4];
    const float* Wd2 = (const float*)d_in[5];
    const float* bd2 = (const float*)d_in[6];
    const float* Wg1 = (const float*)d_in[7];
    const float* bg1 = (const float*)d_in[8];
    const float* Wg2 = (const float*)d_in[9];
    const float* bg2 = (const float*)d_in[10];
    float* out = (float*)d_out;

    cudaFuncSetAttribute(sde_kernel, cudaFuncAttributeMaxDynamicSharedMemorySize,
                         SMEM_BYTES);
    sde_kernel<<<NCTAS, NTHREADS, SMEM_BYTES>>>(x0, noise, Wd1, bd1, Wd2, bd2,
                                                Wg1, bg1, Wg2, bg2, out);
}

// round 17
// speedup vs baseline: 1.6197x; 1.6197x over previous
#include <cuda_runtime.h>
#include <cuda_bf16.h>
#include <cstdint>

#define BATCH 8192
#define NSTEPS 100
#define NCTAS 128
#define NTHREADS 512
#define DT_C 0.01f
#define SQDT_C 0.1f

// float-unit offsets. Matrices stored as "kline planes": one kline = 16 bf16
// of K = 8 u32 units (32B), unit-pairs (u,u+4) adjacent; rows contiguous.
// Groups: warps 4g..4g+3 own rows 16g..16g+15 (disjoint regions of
// X/XL/H/STG; weights shared read-only; private named barriers).
#define OFF_X    0        // x hi bf16: 4 klines x 64 rows x 8
#define OFF_XL   2048     // x lo bf16 (residual)
#define OFF_HD   4096     // h drift bf16: 8 klines x 64 x 8
#define OFF_HG   8192
#define OFF_W1DH 12288    // W1^T planes: 4 klines x 128 x 8 (hi/lo pairs)
#define OFF_W1DL 16384
#define OFF_W1GH 20480
#define OFF_W1GL 24576
#define OFF_W2DH 28672    // W2^T planes: 8 klines x 64 x 8
#define OFF_W2DL 32768
#define OFF_W2GH 36864
#define OFF_W2GL 40960
#define OFF_STG  45056    // g accum staging, 8 x 512 fp32 (2 per group)
#define OFF_B1D  49152
#define OFF_B1G  49280
#define OFF_B2D  49408
#define OFF_B2G  49472
#define SMEM_FLOATS 49536
#define SMEM_BYTES (SMEM_FLOATS * 4)

__device__ __forceinline__ int slot8(int u) { return 2 * (u & 3) + (u >> 2); }
__device__ __forceinline__ uint32_t pack_bf16x2(float lo, float hi) {
    uint32_t r;
    asm("cvt.rn.bf16x2.f32 %0, %1, %2;" : "=r"(r) : "f"(hi), "f"(lo));
    return r;
}
// accurate tanh: 1 - 2/(e^{2x}+1)
__device__ __forceinline__ float tanh_fast(float x) {
    float t = __expf(2.0f * x);
    return 1.0f - __fdividef(2.0f, t + 1.0f);
}
__device__ __forceinline__ void mma16(float* c, uint32_t a0, uint32_t a1,
                                      uint32_t a2, uint32_t a3, uint32_t b0,
                                      uint32_t b1) {
    asm volatile(
        "mma.sync.aligned.m16n8k16.row.col.f32.bf16.bf16.f32 "
        "{%0,%1,%2,%3},{%4,%5,%6,%7},{%8,%9},{%0,%1,%2,%3};\n"
        : "+f"(c[0]), "+f"(c[1]), "+f"(c[2]), "+f"(c[3])
        : "r"(a0), "r"(a1), "r"(a2), "r"(a3), "r"(b0), "r"(b1));
}
// split (v0,v1) into hi/lo bf16x2 words; hi+lo reconstructs v to ~2^-17
__device__ __forceinline__ void wsplit(float v0, float v1, uint32_t& hi,
                                       uint32_t& lo) {
    hi = pack_bf16x2(v0, v1);
    __nv_bfloat162 h2 = *(__nv_bfloat162*)&hi;
    lo = pack_bf16x2(v0 - __bfloat162float(h2.x), v1 - __bfloat162float(h2.y));
}
__device__ __forceinline__ void barsync(int id) {
    asm volatile("bar.sync %0, %1;" ::"r"(id), "r"(128) : "memory");
}
__device__ __forceinline__ void bararrive(int id) {
    asm volatile("bar.arrive %0, %1;" ::"r"(id), "r"(128) : "memory");
}

__global__ void __launch_bounds__(NTHREADS, 1) sde_kernel(
    const float* __restrict__ x0, const float* __restrict__ noise,
    const float* __restrict__ Wd1, const float* __restrict__ bd1,
    const float* __restrict__ Wd2, const float* __restrict__ bd2,
    const float* __restrict__ Wg1, const float* __restrict__ bg1,
    const float* __restrict__ Wg2, const float* __restrict__ bg2,
    float* __restrict__ out) {
    extern __shared__ float sm[];
    const int tid = threadIdx.x;
    const int warp = tid >> 5, lane = tid & 31, g = lane >> 2, tg = lane & 3;
    const int rowBase = blockIdx.x * 64;
    const int grp = warp >> 2;    // group: rows 16*grp .. 16*grp+15
    const int wg = warp & 3;      // warp within group

    // ── init: W1 planes (hi/lo) ─────────────────────────────────────
    for (int i = tid; i < 4096; i += NTHREADS) {  // pairs (k,k+1) x n
        int n = i & 127, kp = i >> 7, k = 2 * kp;
        int idx = (kp >> 3) * 1024 + n * 8 + slot8(kp & 7);
        uint32_t hi, lo;
        wsplit(Wd1[k * 128 + n], Wd1[(k + 1) * 128 + n], hi, lo);
        *(uint32_t*)&sm[OFF_W1DH + idx] = hi;
        *(uint32_t*)&sm[OFF_W1DL + idx] = lo;
        wsplit(Wg1[k * 128 + n], Wg1[(k + 1) * 128 + n], hi, lo);
        *(uint32_t*)&sm[OFF_W1GH + idx] = hi;
        *(uint32_t*)&sm[OFF_W1GL + idx] = lo;
    }
    // W2 planes
    for (int i = tid; i < 4096; i += NTHREADS) {
        int n = i & 63, kp = i >> 6, k = 2 * kp;
        int idx = (kp >> 3) * 512 + n * 8 + slot8(kp & 7);
        uint32_t hi, lo;
        wsplit(Wd2[k * 64 + n], Wd2[(k + 1) * 64 + n], hi, lo);
        *(uint32_t*)&sm[OFF_W2DH + idx] = hi;
        *(uint32_t*)&sm[OFF_W2DL + idx] = lo;
        wsplit(Wg2[k * 64 + n], Wg2[(k + 1) * 64 + n], hi, lo);
        *(uint32_t*)&sm[OFF_W2GH + idx] = hi;
        *(uint32_t*)&sm[OFF_W2GL + idx] = lo;
    }
    for (int i = tid; i < 128; i += NTHREADS) {
        sm[OFF_B1D + i] = bd1[i];
        sm[OFF_B1G + i] = bg1[i];
    }
    for (int i = tid; i < 64; i += NTHREADS) {
        sm[OFF_B2D + i] = bd2[i];
        sm[OFF_B2G + i] = bg2[i];
    }
    // x0 -> hi/lo bf16 planes + out[0]
    for (int i = tid; i < 2048; i += NTHREADS) {  // pairs
        int r = i >> 5, cp = i & 31, c = 2 * cp;
        float v0 = x0[(rowBase + r) * 64 + c];
        float v1 = x0[(rowBase + r) * 64 + c + 1];
        int idx = (cp >> 3) * 512 + r * 8 + slot8(cp & 7);
        uint32_t hi, lo;
        wsplit(v0, v1, hi, lo);
        *(uint32_t*)&sm[OFF_X + idx] = hi;
        *(uint32_t*)&sm[OFF_XL + idx] = lo;
        *(float2*)&out[(rowBase + r) * 64 + c] = make_float2(v0, v1);
    }

    // phase A (4 warps/group): 16r x 32c tile; warp wg -> klines 2wg,2wg+1
    // phase B (per group): warps 0,1 = drift(f), 2,3 = diffusion(g),
    //   tile 16x32 over (16 x 64); col half = wg&1
    const int wq = wg & 1;
    const int bR = 16 * grp, bC = 32 * wq;
    const bool isF = (wg < 2);
    const int bar1 = 3 * grp + 1, bar2 = 3 * grp + 2, bar3 = 3 * grp + 3;

    // fp32 x state lives in f-warp registers (2 warps x 16 elems per group)
    float2 xr[4][2];  // [n][rg]: cols bC+8n+2tg, rows bR+8rg+g
    if (isF) {
#pragma unroll
        for (int n = 0; n < 4; n++)
#pragma unroll
            for (int rg = 0; rg < 2; rg++) {
                int row = rowBase + bR + 8 * rg + g;
                xr[n][rg] =
                    *(const float2*)&x0[row * 64 + bC + 8 * n + 2 * tg];
            }
    }
    __syncthreads();

#pragma unroll 1
    for (int step = 0; step < NSTEPS; ++step) {
        // ── phase A: h_d, h_g = tanh(x@W1 + b1); 16x32 tile per warp ─
        // error-compensated: Ah*Wh + Ah*Wl + Al*Wh, d/g interleaved to
        // break accumulator RAW chains (per-acc order unchanged).
        {
            float ca[2][4][4];  // [mat][nn][4]
#pragma unroll
            for (int a_ = 0; a_ < 2; a_++)
#pragma unroll
                for (int b_ = 0; b_ < 4; b_++)
#pragma unroll
                    for (int j = 0; j < 4; j++) ca[a_][b_][j] = 0.f;
#pragma unroll
            for (int kl = 0; kl < 4; kl++) {
                int r = 16 * grp + g;
                uint2 ah0 = *(const uint2*)(sm + OFF_X + kl * 512 + r * 8 + 2 * tg);
                uint2 ah1 = *(const uint2*)(sm + OFF_X + kl * 512 + (r + 8) * 8 + 2 * tg);
                uint2 al0 = *(const uint2*)(sm + OFF_XL + kl * 512 + r * 8 + 2 * tg);
                uint2 al1 = *(const uint2*)(sm + OFF_XL + kl * 512 + (r + 8) * 8 + 2 * tg);
#pragma unroll
                for (int nn = 0; nn < 4; nn++) {
                    int wr = kl * 1024 + (32 * wg + 8 * nn + g) * 8 + 2 * tg;
                    uint2 bdh = *(const uint2*)(sm + OFF_W1DH + wr);
                    uint2 bdl = *(const uint2*)(sm + OFF_W1DL + wr);
                    uint2 bgh = *(const uint2*)(sm + OFF_W1GH + wr);
                    uint2 bgl = *(const uint2*)(sm + OFF_W1GL + wr);
                    mma16(ca[0][nn], ah0.x, ah1.x, ah0.y, ah1.y, bdh.x, bdh.y);
                    mma16(ca[1][nn], ah0.x, ah1.x, ah0.y, ah1.y, bgh.x, bgh.y);
                    mma16(ca[0][nn], ah0.x, ah1.x, ah0.y, ah1.y, bdl.x, bdl.y);
                    mma16(ca[1][nn], ah0.x, ah1.x, ah0.y, ah1.y, bgl.x, bgl.y);
                    mma16(ca[0][nn], al0.x, al1.x, al0.y, al1.y, bdh.x, bdh.y);
                    mma16(ca[1][nn], al0.x, al1.x, al0.y, al1.y, bgh.x, bgh.y);
                }
            }
            // epilogue: bias + tanh + pack + store (klines 2wg, 2wg+1)
#pragma unroll
            for (int mat = 0; mat < 2; mat++) {
                float* hpb = sm + (mat ? OFF_HG : OFF_HD);
                const float* b1 = sm + (mat ? OFF_B1G : OFF_B1D);
#pragma unroll
                for (int hn = 0; hn < 2; hn++) {
                    int kline = 2 * wg + hn;
                    int cb0 = 32 * wg + 16 * hn + 2 * tg;
                    float b00 = b1[cb0], b01 = b1[cb0 + 1];
                    float b10 = b1[cb0 + 8], b11 = b1[cb0 + 9];
#pragma unroll
                    for (int rg = 0; rg < 2; rg++) {
                        int row = 16 * grp + 8 * rg + g;
                        float c0 = tanh_fast(ca[mat][2 * hn][2 * rg] + b00);
                        float c1 = tanh_fast(ca[mat][2 * hn][2 * rg + 1] + b01);
                        float c2 = tanh_fast(ca[mat][2 * hn + 1][2 * rg] + b10);
                        float c3 = tanh_fast(ca[mat][2 * hn + 1][2 * rg + 1] + b11);
                        *(uint2*)(hpb + kline * 512 + row * 8 + 2 * tg) =
                            make_uint2(pack_bf16x2(c0, c1), pack_bf16x2(c2, c3));
                    }
                }
            }
        }
        // ── noise: direct LDG into f-warp registers (hidden under B) ─
        float2 nzv[2][2][2];  // [np][rg][0:cc0, 1:cc1]
        if (isF) {
            const float* nzp = noise + ((size_t)step * BATCH + rowBase) * 64;
#pragma unroll
            for (int np = 0; np < 2; np++)
#pragma unroll
                for (int rg = 0; rg < 2; rg++) {
                    int row = bR + 8 * rg + g;
                    int cc0 = bC + 16 * np + 2 * tg;
                    nzv[np][rg][0] = *(const float2*)(nzp + row * 64 + cc0);
                    nzv[np][rg][1] = *(const float2*)(nzp + row * 64 + cc0 + 8);
                }
        }
        barsync(bar1);  // S1 (group-scope): this group's h ready

        // ── phase B: y = h @ W2 (W hi+lo), 16x32 tile per warp ──────
        // n-pairs interleaved (hi0,hi1,lo0,lo1) to break RAW chains.
        float cb[4][4];
        {
            const float* hp = sm + (isF ? OFF_HD : OFF_HG);
            const float* w2h = sm + (isF ? OFF_W2DH : OFF_W2GH);
            const float* w2l = sm + (isF ? OFF_W2DL : OFF_W2GL);
#pragma unroll
            for (int n = 0; n < 4; n++)
#pragma unroll
                for (int j = 0; j < 4; j++) cb[n][j] = 0.f;
#pragma unroll
            for (int kl = 0; kl < 8; kl++) {
                uint2 a0 = *(const uint2*)(hp + kl * 512 + (bR + g) * 8 + 2 * tg);
                uint2 a1 = *(const uint2*)(hp + kl * 512 + (bR + 8 + g) * 8 + 2 * tg);
#pragma unroll
                for (int pr = 0; pr < 2; pr++) {
                    int n0 = 2 * pr, n1 = n0 + 1;
                    int wr0 = kl * 512 + (bC + 8 * n0 + g) * 8 + 2 * tg;
                    int wr1 = kl * 512 + (bC + 8 * n1 + g) * 8 + 2 * tg;
                    uint2 bh0 = *(const uint2*)(w2h + wr0);
                    uint2 bl0 = *(const uint2*)(w2l + wr0);
                    uint2 bh1 = *(const uint2*)(w2h + wr1);
                    uint2 bl1 = *(const uint2*)(w2l + wr1);
                    mma16(cb[n0], a0.x, a1.x, a0.y, a1.y, bh0.x, bh0.y);
                    mma16(cb[n1], a0.x, a1.x, a0.y, a1.y, bh1.x, bh1.y);
                    mma16(cb[n0], a0.x, a1.x, a0.y, a1.y, bl0.x, bl0.y);
                    mma16(cb[n1], a0.x, a1.x, a0.y, a1.y, bl1.x, bl1.y);
                }
            }
        }
        if (!isF) {
            // raw g accums -> staging (f-warp of same wq+grp reads it)
#pragma unroll
            for (int n = 0; n < 4; n++)
                *(float4*)(sm + OFF_STG + (grp * 2 + wq) * 512 + n * 128 +
                           lane * 4) = *(float4*)cb[n];
            bararrive(bar2);
        } else {
            barsync(bar2);  // wait this group's g
            // ── combine: x += (f+bd2)*dt + (g+bg2)*dw*sqrt(dt) ──────
            float* op = out + ((size_t)(step + 1) * BATCH + rowBase) * 64;
            const float* gst =
                sm + OFF_STG + (grp * 2 + wq) * 512 + lane * 4;
            float4 gv[4];
#pragma unroll
            for (int n = 0; n < 4; n++) gv[n] = *(const float4*)(gst + n * 128);
#pragma unroll
            for (int np = 0; np < 2; np++) {
                int n0 = 2 * np, n1 = n0 + 1;
                int cc0 = bC + 8 * n0 + 2 * tg, cc1 = cc0 + 8;
                float bd0 = sm[OFF_B2D + cc0], bd1v = sm[OFF_B2D + cc0 + 1];
                float bd2_ = sm[OFF_B2D + cc1], bd3 = sm[OFF_B2D + cc1 + 1];
                float bg0 = sm[OFF_B2G + cc0], bg1v = sm[OFF_B2G + cc0 + 1];
                float bg2_ = sm[OFF_B2G + cc1], bg3 = sm[OFF_B2G + cc1 + 1];
#pragma unroll
                for (int rg = 0; rg < 2; rg++) {
                    int row = bR + 8 * rg + g;
                    float2 nz0 = nzv[np][rg][0];
                    float2 nz1 = nzv[np][rg][1];
                    float f0 = cb[n0][2 * rg] + bd0, f1 = cb[n0][2 * rg + 1] + bd1v;
                    float f2 = cb[n1][2 * rg] + bd2_, f3 = cb[n1][2 * rg + 1] + bd3;
                    float gg0 = (rg ? gv[n0].z : gv[n0].x) + bg0;
                    float gg1 = (rg ? gv[n0].w : gv[n0].y) + bg1v;
                    float gg2 = (rg ? gv[n1].z : gv[n1].x) + bg2_;
                    float gg3 = (rg ? gv[n1].w : gv[n1].y) + bg3;
                    float xn0 = xr[n0][rg].x + f0 * DT_C + gg0 * (nz0.x * SQDT_C);
                    float xn1 = xr[n0][rg].y + f1 * DT_C + gg1 * (nz0.y * SQDT_C);
                    float xn2 = xr[n1][rg].x + f2 * DT_C + gg2 * (nz1.x * SQDT_C);
                    float xn3 = xr[n1][rg].y + f3 * DT_C + gg3 * (nz1.y * SQDT_C);
                    xr[n0][rg] = make_float2(xn0, xn1);
                    xr[n1][rg] = make_float2(xn2, xn3);
                    *(float2*)(op + row * 64 + cc0) = make_float2(xn0, xn1);
                    *(float2*)(op + row * 64 + cc1) = make_float2(xn2, xn3);
                    // refresh hi/lo bf16 x planes (kline = 2*wq + np)
                    uint32_t h01, l01, h23, l23;
                    wsplit(xn0, xn1, h01, l01);
                    wsplit(xn2, xn3, h23, l23);
                    int xi = (2 * wq + np) * 512 + row * 8 + 2 * tg;
                    *(uint2*)(sm + OFF_X + xi) = make_uint2(h01, h23);
                    *(uint2*)(sm + OFF_XL + xi) = make_uint2(l01, l23);
                }
            }
        }
        barsync(bar3);  // S2 (group-scope): this group's x ready
    }
}

extern "C" void kernel_launch(void* const* d_in, const int* in_sizes, int n_in,
                              void* d_out, int out_size) {
    (void)in_sizes; (void)n_in; (void)out_size;
    const float* x0 = (const float*)d_in[0];
    // d_in[1] = t_span (unused)
    const float* noise = (const float*)d_in[2];
    const float* Wd1 = (const float*)d_in[3];
    const float* bd1 = (const float*)d_in[4];
    const float* Wd2 = (const float*)d_in[5];
    const float* bd2 = (const float*)d_in[6];
    const float* Wg1 = (const float*)d_in[7];
    const float* bg1 = (const float*)d_in[8];
    const float* Wg2 = (const float*)d_in[9];
    const float* bg2 = (const float*)d_in[10];
    float* out = (float*)d_out;

    cudaFuncSetAttribute(sde_kernel, cudaFuncAttributeMaxDynamicSharedMemorySize,
                         SMEM_BYTES);
    sde_kernel<<<NCTAS, NTHREADS, SMEM_BYTES>>>(x0, noise, Wd1, bd1, Wd2, bd2,
                                                Wg1, bg1, Wg2, bg2, out);
}